// round 7
// baseline (speedup 1.0000x reference)
#include <cuda_runtime.h>
#include <cstdint>

#define NN 100000
#define HH 128
#define EE 1600000
#define OUTD 64
#define ALPHA_C 0.6f
#define BETA_C 0.1f   // (1-ALPHA)/L

// ---------------- scratch (device globals: allocation-free) ----------------
__device__ float g_Z[(size_t)NN * HH];      // current layer activations
__device__ float g_y[(size_t)NN * HH];      // y = (Z@W)*dis[row]
__device__ float g_zinit[(size_t)NN * HH];
__device__ float g_zsum[(size_t)NN * HH];
__device__ float g_dis[NN];
__device__ int   g_deg[NN];
__device__ int   g_cnt[NN];
__device__ int   g_rowptr[NN];
__device__ int   g_col[EE];
__device__ int   g_bsum[128];
__device__ int   g_is64;

// ---------------- f32x2 helpers ----------------
__device__ __forceinline__ unsigned long long bcast2(float v) {
    unsigned long long r;
    asm("mov.b64 %0, {%1, %1};" : "=l"(r) : "f"(v));
    return r;
}
__device__ __forceinline__ void fma2(unsigned long long& acc, unsigned long long a,
                                     unsigned long long b) {
    asm("fma.rn.f32x2 %0, %1, %2, %0;" : "+l"(acc) : "l"(a), "l"(b));
}
__device__ __forceinline__ float2 unpk(unsigned long long v) {
    float2 r;
    asm("mov.b64 {%0, %1}, %2;" : "=f"(r.x), "=f"(r.y) : "l"(v));
    return r;
}

// ---------------- edge dtype detection ----------------
__global__ void k_detect(const void* ei) {
    if (threadIdx.x == 0) {
        const long long* p = (const long long*)ei;
        int is64 = 1;
        for (int i = 0; i < 64; i++) {
            long long v = p[i];
            if (v < 0 || v >= NN) { is64 = 0; break; }
        }
        g_is64 = is64;
    }
}

__device__ __forceinline__ int edge_at(const void* ei, long long i) {
    return g_is64 ? (int)((const long long*)ei)[i] : ((const int*)ei)[i];
}

// ---------------- CSR build ----------------
__global__ void k_zero() {
    int i = blockIdx.x * blockDim.x + threadIdx.x;
    if (i < NN) { g_deg[i] = 0; g_cnt[i] = 0; }
}

__global__ void k_hist(const void* ei) {
    int e = blockIdx.x * blockDim.x + threadIdx.x;
    if (e < EE) atomicAdd(&g_deg[edge_at(ei, (long long)EE + e)], 1);
}

__global__ void k_dis() {
    int i = blockIdx.x * blockDim.x + threadIdx.x;
    if (i < NN) g_dis[i] = rsqrtf((float)g_deg[i] + 1.0f);
}

__global__ void k_scan1() {
    __shared__ int sm[256];
    int b = blockIdx.x, t = threadIdx.x;
    int base = b * 1024 + t * 4;
    int v[4];
#pragma unroll
    for (int j = 0; j < 4; j++) {
        int i = base + j;
        v[j] = (i < NN) ? g_deg[i] : 0;
    }
    int s = v[0] + v[1] + v[2] + v[3];
    sm[t] = s;
    __syncthreads();
    for (int off = 1; off < 256; off <<= 1) {
        int x = sm[t];
        if (t >= off) x += sm[t - off];
        __syncthreads();
        sm[t] = x;
        __syncthreads();
    }
    int ex = sm[t] - s;
    int run = 0;
#pragma unroll
    for (int j = 0; j < 4; j++) {
        int i = base + j;
        if (i < NN) g_rowptr[i] = ex + run;
        run += v[j];
    }
    if (t == 255) g_bsum[b] = sm[255];
}

__global__ void k_scan2(int nb) {
    __shared__ int sm[128];
    int t = threadIdx.x;
    int v = (t < nb) ? g_bsum[t] : 0;
    sm[t] = v;
    __syncthreads();
    for (int off = 1; off < 128; off <<= 1) {
        int x = sm[t];
        if (t >= off) x += sm[t - off];
        __syncthreads();
        sm[t] = x;
        __syncthreads();
    }
    g_bsum[t] = sm[t] - v;
}

__global__ void k_scan3() {
    int i = blockIdx.x * blockDim.x + threadIdx.x;
    if (i < NN) g_rowptr[i] += g_bsum[i >> 10];
}

__global__ void k_fill(const void* ei) {
    int e = blockIdx.x * blockDim.x + threadIdx.x;
    if (e >= EE) return;
    int s = edge_at(ei, e);
    int d = edge_at(ei, (long long)EE + e);
    int pos = g_rowptr[d] + atomicAdd(&g_cnt[d], 1);
    g_col[pos] = s;
}

// ---------------- GEMM: 128 x 128 @ 128 x BN, all-resident SMEM ----------------
// A tile (128x128, 64KB) + full W (128xBN) loaded once; one sync; straight K loop.
// Thread tile 8 rows x TN cols, accumulators packed over column pairs (f32x2).
// MODE 0: C = x@W + bias  -> g_Z, g_zinit, g_zsum=0
// MODE 1: g_y = (g_Z@W) * dis[row]
// MODE 2: out = (ALPHA*zinit + BETA*zsum)@W + bias
template <int BN, int TN, int MODE>
__global__ void __launch_bounds__(256, 1) k_mm(const float* __restrict__ A,
                                               const float* __restrict__ W,
                                               const float* __restrict__ bias,
                                               float* __restrict__ C) {
    extern __shared__ float sm[];
    float* As = sm;               // 128*128 floats
    float* Bs = sm + 128 * 128;   // 128*BN floats

    int tid = threadIdx.x;
    int row0 = blockIdx.x * 128;

    // ---- load A tile (identity layout, coalesced) ----
#pragma unroll
    for (int it = 0; it < 16; it++) {
        int f4 = it * 256 + tid;        // float4 index 0..4095
        int r = f4 >> 5;                // row 0..127
        int grow = row0 + r;
        float4 v = make_float4(0.f, 0.f, 0.f, 0.f);
        if (grow < NN) {
            size_t off = (size_t)grow * 128 + ((f4 & 31) << 2);
            if (MODE == 0) {
                v = *(const float4*)(A + off);
            } else if (MODE == 1) {
                v = *(const float4*)(g_Z + off);
            } else {
                float4 zi = *(const float4*)(g_zinit + off);
                float4 zs = *(const float4*)(g_zsum + off);
                v.x = ALPHA_C * zi.x + BETA_C * zs.x;
                v.y = ALPHA_C * zi.y + BETA_C * zs.y;
                v.z = ALPHA_C * zi.z + BETA_C * zs.z;
                v.w = ALPHA_C * zi.w + BETA_C * zs.w;
            }
        }
        *(float4*)&As[(size_t)f4 << 2] = v;
    }
    // ---- load full B (identity copy) ----
#pragma unroll
    for (int it = 0; it < (128 * BN) / 1024; it++) {
        int f4 = it * 256 + tid;
        *(float4*)&Bs[(size_t)f4 << 2] = *(const float4*)(W + ((size_t)f4 << 2));
    }
    __syncthreads();

    int rg = tid >> 4;       // 0..15 -> 8-row group
    int cg = tid & 15;       // 0..15 -> TN-col group
    int rb = rg * 8;
    int cb = cg * TN;

    unsigned long long acc2[8][TN / 2];
#pragma unroll
    for (int i = 0; i < 8; i++)
#pragma unroll
        for (int c = 0; c < TN / 2; c++) acc2[i][c] = 0ULL;

#pragma unroll 2
    for (int kk = 0; kk < 32; kk++) {
        float4 af[8];
#pragma unroll
        for (int i = 0; i < 8; i++)
            af[i] = *(float4*)&As[(rb + i) * 128 + kk * 4];
#pragma unroll
        for (int j = 0; j < 4; j++) {
            int k = kk * 4 + j;
            unsigned long long bb[TN / 2];
            if (TN == 8) {
                ulonglong2 p0 = *(ulonglong2*)&Bs[k * BN + cb];
                ulonglong2 p1 = *(ulonglong2*)&Bs[k * BN + cb + 4];
                bb[0] = p0.x; bb[1] = p0.y; bb[2] = p1.x; bb[3] = p1.y;
            } else {
                ulonglong2 p0 = *(ulonglong2*)&Bs[k * BN + cb];
                bb[0] = p0.x; bb[1] = p0.y;
            }
#pragma unroll
            for (int i = 0; i < 8; i++) {
                float a = (j == 0) ? af[i].x : (j == 1) ? af[i].y
                        : (j == 2) ? af[i].z : af[i].w;
                unsigned long long a2 = bcast2(a);
#pragma unroll
                for (int c = 0; c < TN / 2; c++) fma2(acc2[i][c], a2, bb[c]);
            }
        }
    }

    // ---- epilogue ----
    float4 bv0 = make_float4(0.f, 0.f, 0.f, 0.f), bv1 = bv0;
    if (MODE != 1) {
        bv0 = *(const float4*)(bias + cb);
        if (TN == 8) bv1 = *(const float4*)(bias + cb + 4);
    }
#pragma unroll
    for (int i = 0; i < 8; i++) {
        int grow = row0 + rb + i;
        if (grow >= NN) continue;
        float2 u[TN / 2];
#pragma unroll
        for (int c = 0; c < TN / 2; c++) u[c] = unpk(acc2[i][c]);
        if (MODE == 0) {
            size_t off = (size_t)grow * 128 + cb;
            float4 v0 = make_float4(u[0].x + bv0.x, u[0].y + bv0.y,
                                    u[1].x + bv0.z, u[1].y + bv0.w);
            float4 v1 = make_float4(u[2].x + bv1.x, u[2].y + bv1.y,
                                    u[3].x + bv1.z, u[3].y + bv1.w);
            *(float4*)(g_Z + off) = v0;
            *(float4*)(g_Z + off + 4) = v1;
            *(float4*)(g_zinit + off) = v0;
            *(float4*)(g_zinit + off + 4) = v1;
            *(float4*)(g_zsum + off) = make_float4(0.f, 0.f, 0.f, 0.f);
            *(float4*)(g_zsum + off + 4) = make_float4(0.f, 0.f, 0.f, 0.f);
        } else if (MODE == 1) {
            float d = g_dis[grow];
            size_t off = (size_t)grow * 128 + cb;
            *(float4*)(g_y + off) = make_float4(u[0].x * d, u[0].y * d,
                                                u[1].x * d, u[1].y * d);
            *(float4*)(g_y + off + 4) = make_float4(u[2].x * d, u[2].y * d,
                                                    u[3].x * d, u[3].y * d);
        } else {
            size_t off = (size_t)grow * OUTD + cb;
            *(float4*)(C + off) = make_float4(u[0].x + bv0.x, u[0].y + bv0.y,
                                              u[1].x + bv0.z, u[1].y + bv0.w);
        }
    }
}

// ---------------- aggregation: one warp per dst node ----------------
// Z[d] = relu( dis[d]*( sum_{s in nbr(d)} y[s] + y[d] ) + b ); zsum[d] += Z[d]
__global__ void k_agg(const float* __restrict__ bias) {
    int warp = (blockIdx.x * blockDim.x + threadIdx.x) >> 5;
    int lane = threadIdx.x & 31;
    if (warp >= NN) return;
    int d = warp;
    int start = g_rowptr[d];
    int len = g_deg[d];
    const float4* y4 = (const float4*)g_y;
    float4 acc = y4[(size_t)d * 32 + lane];  // self term y[d]
    int end = start + len;
    for (int j0 = start; j0 < end; j0 += 32) {
        int c = (j0 + lane < end) ? g_col[j0 + lane] : 0;
        int m = end - j0; if (m > 32) m = 32;
        for (int t = 0; t < m; t++) {
            int s = __shfl_sync(0xffffffffu, c, t);
            float4 v = y4[(size_t)s * 32 + lane];
            acc.x += v.x; acc.y += v.y; acc.z += v.z; acc.w += v.w;
        }
    }
    float dd = g_dis[d];
    float4 b4 = ((const float4*)bias)[lane];
    float4 o;
    o.x = fmaxf(fmaf(dd, acc.x, b4.x), 0.f);
    o.y = fmaxf(fmaf(dd, acc.y, b4.y), 0.f);
    o.z = fmaxf(fmaf(dd, acc.z, b4.z), 0.f);
    o.w = fmaxf(fmaf(dd, acc.w, b4.w), 0.f);
    ((float4*)g_Z)[(size_t)d * 32 + lane] = o;
    float4* zs4 = (float4*)g_zsum;
    float4 zs = zs4[(size_t)d * 32 + lane];
    zs.x += o.x; zs.y += o.y; zs.z += o.z; zs.w += o.w;
    zs4[(size_t)d * 32 + lane] = zs;
}

// ---------------- launch ----------------
extern "C" void kernel_launch(void* const* d_in, const int* in_sizes, int n_in,
                              void* d_out, int out_size) {
    const float* x     = (const float*)d_in[0];
    const void*  ei    = d_in[1];
    const float* W1    = (const float*)d_in[2];
    const float* b1    = (const float*)d_in[3];
    const float* convW = (const float*)d_in[4];
    const float* convB = (const float*)d_in[5];
    const float* W2    = (const float*)d_in[6];
    const float* b2    = (const float*)d_in[7];
    float* out = (float*)d_out;

    const int NB_N = (NN + 255) / 256;
    const int NB_E = (EE + 255) / 256;
    const int NB_SCAN = (NN + 1023) / 1024;
    const int NB_MM = (NN + 127) / 128;       // 782
    const int NB_AGG = (NN * 32 + 255) / 256;

    const int SM128 = (128 * 128 + 128 * 128) * 4;  // 131072
    const int SM64  = (128 * 128 + 128 * 64) * 4;   //  98304
    cudaFuncSetAttribute(k_mm<128, 8, 0>, cudaFuncAttributeMaxDynamicSharedMemorySize, SM128);
    cudaFuncSetAttribute(k_mm<128, 8, 1>, cudaFuncAttributeMaxDynamicSharedMemorySize, SM128);
    cudaFuncSetAttribute(k_mm<64, 4, 2>,  cudaFuncAttributeMaxDynamicSharedMemorySize, SM64);

    // order chosen so launch #4 (the one ncu -s5 -c1 captures) is the mode-0 GEMM
    k_detect<<<1, 32>>>(ei);
    k_zero<<<NB_N, 256>>>();
    k_hist<<<NB_E, 256>>>(ei);
    k_mm<128, 8, 0><<<NB_MM, 256, SM128>>>(x, W1, b1, nullptr);
    k_dis<<<NB_N, 256>>>();
    k_scan1<<<NB_SCAN, 256>>>();
    k_scan2<<<1, 128>>>(NB_SCAN);
    k_scan3<<<NB_N, 256>>>();
    k_fill<<<NB_E, 256>>>(ei);

    for (int l = 0; l < 4; l++) {
        k_mm<128, 8, 1><<<NB_MM, 256, SM128>>>(nullptr, convW + (size_t)l * HH * HH,
                                               nullptr, nullptr);
        k_agg<<<NB_AGG, 256>>>(convB + (size_t)l * HH);
    }

    k_mm<64, 4, 2><<<NB_MM, 256, SM64>>>(nullptr, W2, b2, out);
}

// round 8
// speedup vs baseline: 1.0146x; 1.0146x over previous
#include <cuda_runtime.h>
#include <cstdint>

#define NN 100000
#define HH 128
#define EE 1600000
#define OUTD 64
#define ALPHA_C 0.6f
#define BETA_C 0.1f   // (1-ALPHA)/L

// ---------------- scratch (device globals: allocation-free) ----------------
__device__ float g_Z[(size_t)NN * HH];      // current layer activations
__device__ float g_y[(size_t)NN * HH];      // y = (Z@W)*dis[row]
__device__ float g_zinit[(size_t)NN * HH];
__device__ float g_zsum[(size_t)NN * HH];
__device__ float g_dis[NN];
__device__ int   g_deg[NN];
__device__ int   g_cnt[NN];
__device__ int   g_rowptr[NN];
__device__ int   g_col[EE];
__device__ int   g_bsum[128];
__device__ int   g_is64;

// ---------------- f32x2 helpers ----------------
__device__ __forceinline__ unsigned long long bcast2(float v) {
    unsigned long long r;
    asm("mov.b64 %0, {%1, %1};" : "=l"(r) : "f"(v));
    return r;
}
__device__ __forceinline__ void fma2(unsigned long long& acc, unsigned long long a,
                                     unsigned long long b) {
    asm("fma.rn.f32x2 %0, %1, %2, %0;" : "+l"(acc) : "l"(a), "l"(b));
}
__device__ __forceinline__ float2 unpk(unsigned long long v) {
    float2 r;
    asm("mov.b64 {%0, %1}, %2;" : "=f"(r.x), "=f"(r.y) : "l"(v));
    return r;
}

// ---------------- edge dtype detection ----------------
__global__ void k_detect(const void* ei) {
    if (threadIdx.x == 0) {
        const long long* p = (const long long*)ei;
        int is64 = 1;
        for (int i = 0; i < 64; i++) {
            long long v = p[i];
            if (v < 0 || v >= NN) { is64 = 0; break; }
        }
        g_is64 = is64;
    }
}

__device__ __forceinline__ int edge_at(const void* ei, long long i) {
    return g_is64 ? (int)((const long long*)ei)[i] : ((const int*)ei)[i];
}

// ---------------- CSR build ----------------
__global__ void k_zero() {
    int i = blockIdx.x * blockDim.x + threadIdx.x;
    if (i < NN) { g_deg[i] = 0; g_cnt[i] = 0; }
}

__global__ void k_hist(const void* ei) {
    int e = blockIdx.x * blockDim.x + threadIdx.x;
    if (e < EE) atomicAdd(&g_deg[edge_at(ei, (long long)EE + e)], 1);
}

__global__ void k_dis() {
    int i = blockIdx.x * blockDim.x + threadIdx.x;
    if (i < NN) g_dis[i] = rsqrtf((float)g_deg[i] + 1.0f);
}

__global__ void k_scan1() {
    __shared__ int sm[256];
    int b = blockIdx.x, t = threadIdx.x;
    int base = b * 1024 + t * 4;
    int v[4];
#pragma unroll
    for (int j = 0; j < 4; j++) {
        int i = base + j;
        v[j] = (i < NN) ? g_deg[i] : 0;
    }
    int s = v[0] + v[1] + v[2] + v[3];
    sm[t] = s;
    __syncthreads();
    for (int off = 1; off < 256; off <<= 1) {
        int x = sm[t];
        if (t >= off) x += sm[t - off];
        __syncthreads();
        sm[t] = x;
        __syncthreads();
    }
    int ex = sm[t] - s;
    int run = 0;
#pragma unroll
    for (int j = 0; j < 4; j++) {
        int i = base + j;
        if (i < NN) g_rowptr[i] = ex + run;
        run += v[j];
    }
    if (t == 255) g_bsum[b] = sm[255];
}

__global__ void k_scan2(int nb) {
    __shared__ int sm[128];
    int t = threadIdx.x;
    int v = (t < nb) ? g_bsum[t] : 0;
    sm[t] = v;
    __syncthreads();
    for (int off = 1; off < 128; off <<= 1) {
        int x = sm[t];
        if (t >= off) x += sm[t - off];
        __syncthreads();
        sm[t] = x;
        __syncthreads();
    }
    g_bsum[t] = sm[t] - v;
}

__global__ void k_scan3() {
    int i = blockIdx.x * blockDim.x + threadIdx.x;
    if (i < NN) g_rowptr[i] += g_bsum[i >> 10];
}

__global__ void k_fill(const void* ei) {
    int e = blockIdx.x * blockDim.x + threadIdx.x;
    if (e >= EE) return;
    int s = edge_at(ei, e);
    int d = edge_at(ei, (long long)EE + e);
    int pos = g_rowptr[d] + atomicAdd(&g_cnt[d], 1);
    g_col[pos] = s;
}

// ---------------- GEMM: 128 x 128 @ 128 x BN, all-resident SMEM, 512 thr ----------------
// Thread tile RM rows x 4 cols; col group cg = tid % (BN/4), row group rg = tid / (BN/4).
// BN=128: 32 col groups, rg = warp id (A loads are full-warp broadcast), RM=8.
// BN=64 : 16 col groups, RM=4.
// MODE 0: C = x@W + bias  -> g_Z, g_zinit, g_zsum=0
// MODE 1: g_y = (g_Z@W) * dis[row]
// MODE 2: out = (ALPHA*zinit + BETA*zsum)@W + bias
template <int BN, int MODE>
__global__ void __launch_bounds__(512, 1) k_mm(const float* __restrict__ A,
                                               const float* __restrict__ W,
                                               const float* __restrict__ bias,
                                               float* __restrict__ C) {
    extern __shared__ float sm[];
    float* As = sm;               // 128*128 floats
    float* Bs = sm + 128 * 128;   // 128*BN floats

    constexpr int CPG = BN / 4;            // column groups
    constexpr int RM = 128 * CPG / 512;    // rows per thread (8 or 4)

    int tid = threadIdx.x;
    int row0 = blockIdx.x * 128;

    // ---- load A tile (identity layout, coalesced) ----
#pragma unroll
    for (int it = 0; it < 8; it++) {
        int f4 = it * 512 + tid;        // float4 index 0..4095
        int r = f4 >> 5;                // row 0..127
        int grow = row0 + r;
        float4 v = make_float4(0.f, 0.f, 0.f, 0.f);
        if (grow < NN) {
            size_t off = (size_t)grow * 128 + ((f4 & 31) << 2);
            if (MODE == 0) {
                v = *(const float4*)(A + off);
            } else if (MODE == 1) {
                v = *(const float4*)(g_Z + off);
            } else {
                float4 zi = *(const float4*)(g_zinit + off);
                float4 zs = *(const float4*)(g_zsum + off);
                v.x = ALPHA_C * zi.x + BETA_C * zs.x;
                v.y = ALPHA_C * zi.y + BETA_C * zs.y;
                v.z = ALPHA_C * zi.z + BETA_C * zs.z;
                v.w = ALPHA_C * zi.w + BETA_C * zs.w;
            }
        }
        *(float4*)&As[(size_t)f4 << 2] = v;
    }
    // ---- load full B (identity copy) ----
#pragma unroll
    for (int it = 0; it < (128 * BN) / 2048; it++) {
        int f4 = it * 512 + tid;
        *(float4*)&Bs[(size_t)f4 << 2] = *(const float4*)(W + ((size_t)f4 << 2));
    }
    __syncthreads();

    int cg = tid & (CPG - 1);
    int rg = tid / CPG;
    int rb = rg * RM;
    int cb = cg * 4;

    unsigned long long acc2[RM][2];
#pragma unroll
    for (int i = 0; i < RM; i++) { acc2[i][0] = 0ULL; acc2[i][1] = 0ULL; }

#pragma unroll 2
    for (int kk = 0; kk < 32; kk++) {
        float4 af[RM];
#pragma unroll
        for (int i = 0; i < RM; i++)
            af[i] = *(float4*)&As[(rb + i) * 128 + kk * 4];
#pragma unroll
        for (int j = 0; j < 4; j++) {
            int k = kk * 4 + j;
            ulonglong2 p = *(ulonglong2*)&Bs[k * BN + cb];
#pragma unroll
            for (int i = 0; i < RM; i++) {
                float a = (j == 0) ? af[i].x : (j == 1) ? af[i].y
                        : (j == 2) ? af[i].z : af[i].w;
                unsigned long long a2 = bcast2(a);
                fma2(acc2[i][0], a2, p.x);
                fma2(acc2[i][1], a2, p.y);
            }
        }
    }

    // ---- epilogue ----
    float4 bv = make_float4(0.f, 0.f, 0.f, 0.f);
    if (MODE != 1) bv = *(const float4*)(bias + cb);
#pragma unroll
    for (int i = 0; i < RM; i++) {
        int grow = row0 + rb + i;
        if (grow >= NN) continue;
        float2 u0 = unpk(acc2[i][0]);
        float2 u1 = unpk(acc2[i][1]);
        if (MODE == 0) {
            size_t off = (size_t)grow * 128 + cb;
            float4 v = make_float4(u0.x + bv.x, u0.y + bv.y,
                                   u1.x + bv.z, u1.y + bv.w);
            *(float4*)(g_Z + off) = v;
            *(float4*)(g_zinit + off) = v;
            *(float4*)(g_zsum + off) = make_float4(0.f, 0.f, 0.f, 0.f);
        } else if (MODE == 1) {
            float d = g_dis[grow];
            size_t off = (size_t)grow * 128 + cb;
            *(float4*)(g_y + off) = make_float4(u0.x * d, u0.y * d,
                                                u1.x * d, u1.y * d);
        } else {
            size_t off = (size_t)grow * OUTD + cb;
            *(float4*)(C + off) = make_float4(u0.x + bv.x, u0.y + bv.y,
                                              u1.x + bv.z, u1.y + bv.w);
        }
    }
}

// ---------------- aggregation: one warp per dst node ----------------
// Z[d] = relu( dis[d]*( sum_{s in nbr(d)} y[s] + y[d] ) + b ); zsum[d] += Z[d]
__global__ void k_agg(const float* __restrict__ bias) {
    int warp = (blockIdx.x * blockDim.x + threadIdx.x) >> 5;
    int lane = threadIdx.x & 31;
    if (warp >= NN) return;
    int d = warp;
    int start = g_rowptr[d];
    int len = g_deg[d];
    const float4* y4 = (const float4*)g_y;
    float4 acc = y4[(size_t)d * 32 + lane];  // self term y[d]
    int end = start + len;
    for (int j0 = start; j0 < end; j0 += 32) {
        int c = (j0 + lane < end) ? g_col[j0 + lane] : 0;
        int m = end - j0; if (m > 32) m = 32;
        for (int t = 0; t < m; t++) {
            int s = __shfl_sync(0xffffffffu, c, t);
            float4 v = y4[(size_t)s * 32 + lane];
            acc.x += v.x; acc.y += v.y; acc.z += v.z; acc.w += v.w;
        }
    }
    float dd = g_dis[d];
    float4 b4 = ((const float4*)bias)[lane];
    float4 o;
    o.x = fmaxf(fmaf(dd, acc.x, b4.x), 0.f);
    o.y = fmaxf(fmaf(dd, acc.y, b4.y), 0.f);
    o.z = fmaxf(fmaf(dd, acc.z, b4.z), 0.f);
    o.w = fmaxf(fmaf(dd, acc.w, b4.w), 0.f);
    ((float4*)g_Z)[(size_t)d * 32 + lane] = o;
    float4* zs4 = (float4*)g_zsum;
    float4 zs = zs4[(size_t)d * 32 + lane];
    zs.x += o.x; zs.y += o.y; zs.z += o.z; zs.w += o.w;
    zs4[(size_t)d * 32 + lane] = zs;
}

// ---------------- launch ----------------
extern "C" void kernel_launch(void* const* d_in, const int* in_sizes, int n_in,
                              void* d_out, int out_size) {
    const float* x     = (const float*)d_in[0];
    const void*  ei    = d_in[1];
    const float* W1    = (const float*)d_in[2];
    const float* b1    = (const float*)d_in[3];
    const float* convW = (const float*)d_in[4];
    const float* convB = (const float*)d_in[5];
    const float* W2    = (const float*)d_in[6];
    const float* b2    = (const float*)d_in[7];
    float* out = (float*)d_out;

    const int NB_N = (NN + 255) / 256;
    const int NB_E = (EE + 255) / 256;
    const int NB_SCAN = (NN + 1023) / 1024;
    const int NB_MM = (NN + 127) / 128;       // 782
    const int NB_AGG = (NN * 32 + 255) / 256;

    const int SM128 = (128 * 128 + 128 * 128) * 4;  // 131072
    const int SM64  = (128 * 128 + 128 * 64) * 4;   //  98304
    cudaFuncSetAttribute(k_mm<128, 0>, cudaFuncAttributeMaxDynamicSharedMemorySize, SM128);
    cudaFuncSetAttribute(k_mm<128, 1>, cudaFuncAttributeMaxDynamicSharedMemorySize, SM128);
    cudaFuncSetAttribute(k_mm<64, 2>,  cudaFuncAttributeMaxDynamicSharedMemorySize, SM64);

    // order chosen so launch #4 (the one ncu -s5 -c1 captures) is the mode-0 GEMM
    k_detect<<<1, 32>>>(ei);
    k_zero<<<NB_N, 256>>>();
    k_hist<<<NB_E, 256>>>(ei);
    k_mm<128, 0><<<NB_MM, 512, SM128>>>(x, W1, b1, nullptr);
    k_dis<<<NB_N, 256>>>();
    k_scan1<<<NB_SCAN, 256>>>();
    k_scan2<<<1, 128>>>(NB_SCAN);
    k_scan3<<<NB_N, 256>>>();
    k_fill<<<NB_E, 256>>>(ei);

    for (int l = 0; l < 4; l++) {
        k_mm<128, 1><<<NB_MM, 512, SM128>>>(nullptr, convW + (size_t)l * HH * HH,
                                            nullptr, nullptr);
        k_agg<<<NB_AGG, 256>>>(convB + (size_t)l * HH);
    }

    k_mm<64, 2><<<NB_MM, 512, SM64>>>(nullptr, W2, b2, out);
}

// round 10
// speedup vs baseline: 1.1760x; 1.1591x over previous
#include <cuda_runtime.h>
#include <cuda_fp16.h>
#include <cstdint>

#define NN 100000
#define HH 128
#define EE 1600000
#define OUTD 64
#define ALPHA_C 0.6f
#define BETA_C 0.1f   // (1-ALPHA)/L

// ---------------- scratch (device globals: allocation-free) ----------------
__device__ float  g_Z[(size_t)NN * HH];     // current layer activations (fp32)
__device__ __half g_yh[(size_t)NN * HH];    // y = (Z@W)*dis[row], fp16 storage
__device__ float  g_zinit[(size_t)NN * HH];
__device__ float  g_zsum[(size_t)NN * HH];
__device__ float  g_dis[NN];
__device__ int    g_deg[NN];
__device__ int    g_cnt[NN];
__device__ int    g_rowptr[NN];
__device__ int    g_col[EE];
__device__ int    g_bsum[128];
__device__ int    g_is64;

// ---------------- f32x2 helpers ----------------
__device__ __forceinline__ unsigned long long bcast2(float v) {
    unsigned long long r;
    asm("mov.b64 %0, {%1, %1};" : "=l"(r) : "f"(v));
    return r;
}
__device__ __forceinline__ void fma2(unsigned long long& acc, unsigned long long a,
                                     unsigned long long b) {
    asm("fma.rn.f32x2 %0, %1, %2, %0;" : "+l"(acc) : "l"(a), "l"(b));
}
__device__ __forceinline__ float2 unpk(unsigned long long v) {
    float2 r;
    asm("mov.b64 {%0, %1}, %2;" : "=f"(r.x), "=f"(r.y) : "l"(v));
    return r;
}

// ---------------- edge dtype detection ----------------
__global__ void k_detect(const void* ei) {
    if (threadIdx.x == 0) {
        const long long* p = (const long long*)ei;
        int is64 = 1;
        for (int i = 0; i < 64; i++) {
            long long v = p[i];
            if (v < 0 || v >= NN) { is64 = 0; break; }
        }
        g_is64 = is64;
    }
}

__device__ __forceinline__ int edge_at(const void* ei, long long i) {
    return g_is64 ? (int)((const long long*)ei)[i] : ((const int*)ei)[i];
}

// ---------------- CSR build ----------------
__global__ void k_zero() {
    int i = blockIdx.x * blockDim.x + threadIdx.x;
    if (i < NN) { g_deg[i] = 0; g_cnt[i] = 0; }
}

__global__ void k_hist(const void* ei) {
    int e = blockIdx.x * blockDim.x + threadIdx.x;
    if (e < EE) atomicAdd(&g_deg[edge_at(ei, (long long)EE + e)], 1);
}

__global__ void k_dis() {
    int i = blockIdx.x * blockDim.x + threadIdx.x;
    if (i < NN) g_dis[i] = rsqrtf((float)g_deg[i] + 1.0f);
}

__global__ void k_scan1() {
    __shared__ int sm[256];
    int b = blockIdx.x, t = threadIdx.x;
    int base = b * 1024 + t * 4;
    int v[4];
#pragma unroll
    for (int j = 0; j < 4; j++) {
        int i = base + j;
        v[j] = (i < NN) ? g_deg[i] : 0;
    }
    int s = v[0] + v[1] + v[2] + v[3];
    sm[t] = s;
    __syncthreads();
    for (int off = 1; off < 256; off <<= 1) {
        int x = sm[t];
        if (t >= off) x += sm[t - off];
        __syncthreads();
        sm[t] = x;
        __syncthreads();
    }
    int ex = sm[t] - s;
    int run = 0;
#pragma unroll
    for (int j = 0; j < 4; j++) {
        int i = base + j;
        if (i < NN) g_rowptr[i] = ex + run;
        run += v[j];
    }
    if (t == 255) g_bsum[b] = sm[255];
}

__global__ void k_scan2(int nb) {
    __shared__ int sm[128];
    int t = threadIdx.x;
    int v = (t < nb) ? g_bsum[t] : 0;
    sm[t] = v;
    __syncthreads();
    for (int off = 1; off < 128; off <<= 1) {
        int x = sm[t];
        if (t >= off) x += sm[t - off];
        __syncthreads();
        sm[t] = x;
        __syncthreads();
    }
    g_bsum[t] = sm[t] - v;
}

__global__ void k_scan3() {
    int i = blockIdx.x * blockDim.x + threadIdx.x;
    if (i < NN) g_rowptr[i] += g_bsum[i >> 10];
}

__global__ void k_fill(const void* ei) {
    int e = blockIdx.x * blockDim.x + threadIdx.x;
    if (e >= EE) return;
    int s = edge_at(ei, e);
    int d = edge_at(ei, (long long)EE + e);
    int pos = g_rowptr[d] + atomicAdd(&g_cnt[d], 1);
    g_col[pos] = s;
}

// ---------------- GEMM: 128 x 128 @ 128 x BN, all-resident SMEM, 512 thr ----------------
// MODE 0: C = x@W + bias  -> g_Z, g_zinit, g_zsum=0
// MODE 1: g_yh = fp16( (g_Z@W) * dis[row] )
// MODE 2: out = (ALPHA*zinit + BETA*zsum)@W + bias
template <int BN, int MODE>
__global__ void __launch_bounds__(512, 1) k_mm(const float* __restrict__ A,
                                               const float* __restrict__ W,
                                               const float* __restrict__ bias,
                                               float* __restrict__ C) {
    extern __shared__ float sm[];
    float* As = sm;               // 128*128 floats
    float* Bs = sm + 128 * 128;   // 128*BN floats

    constexpr int CPG = BN / 4;            // column groups
    constexpr int RM = 128 * CPG / 512;    // rows per thread (8 or 4)

    int tid = threadIdx.x;
    int row0 = blockIdx.x * 128;

    // ---- load A tile (identity layout, coalesced) ----
#pragma unroll
    for (int it = 0; it < 8; it++) {
        int f4 = it * 512 + tid;        // float4 index 0..4095
        int r = f4 >> 5;                // row 0..127
        int grow = row0 + r;
        float4 v = make_float4(0.f, 0.f, 0.f, 0.f);
        if (grow < NN) {
            size_t off = (size_t)grow * 128 + ((f4 & 31) << 2);
            if (MODE == 0) {
                v = *(const float4*)(A + off);
            } else if (MODE == 1) {
                v = *(const float4*)(g_Z + off);
            } else {
                float4 zi = *(const float4*)(g_zinit + off);
                float4 zs = *(const float4*)(g_zsum + off);
                v.x = ALPHA_C * zi.x + BETA_C * zs.x;
                v.y = ALPHA_C * zi.y + BETA_C * zs.y;
                v.z = ALPHA_C * zi.z + BETA_C * zs.z;
                v.w = ALPHA_C * zi.w + BETA_C * zs.w;
            }
        }
        *(float4*)&As[(size_t)f4 << 2] = v;
    }
    // ---- load full B (identity copy) ----
#pragma unroll
    for (int it = 0; it < (128 * BN) / 2048; it++) {
        int f4 = it * 512 + tid;
        *(float4*)&Bs[(size_t)f4 << 2] = *(const float4*)(W + ((size_t)f4 << 2));
    }
    __syncthreads();

    int cg = tid & (CPG - 1);
    int rg = tid / CPG;
    int rb = rg * RM;
    int cb = cg * 4;

    unsigned long long acc2[RM][2];
#pragma unroll
    for (int i = 0; i < RM; i++) { acc2[i][0] = 0ULL; acc2[i][1] = 0ULL; }

#pragma unroll 4
    for (int kk = 0; kk < 32; kk++) {
        float4 af[RM];
#pragma unroll
        for (int i = 0; i < RM; i++)
            af[i] = *(float4*)&As[(rb + i) * 128 + kk * 4];
#pragma unroll
        for (int j = 0; j < 4; j++) {
            int k = kk * 4 + j;
            ulonglong2 p = *(ulonglong2*)&Bs[k * BN + cb];
#pragma unroll
            for (int i = 0; i < RM; i++) {
                float a = (j == 0) ? af[i].x : (j == 1) ? af[i].y
                        : (j == 2) ? af[i].z : af[i].w;
                unsigned long long a2 = bcast2(a);
                fma2(acc2[i][0], a2, p.x);
                fma2(acc2[i][1], a2, p.y);
            }
        }
    }

    // ---- epilogue ----
    float4 bv = make_float4(0.f, 0.f, 0.f, 0.f);
    if (MODE != 1) bv = *(const float4*)(bias + cb);
#pragma unroll
    for (int i = 0; i < RM; i++) {
        int grow = row0 + rb + i;
        if (grow >= NN) continue;
        float2 u0 = unpk(acc2[i][0]);
        float2 u1 = unpk(acc2[i][1]);
        if (MODE == 0) {
            size_t off = (size_t)grow * 128 + cb;
            float4 v = make_float4(u0.x + bv.x, u0.y + bv.y,
                                   u1.x + bv.z, u1.y + bv.w);
            *(float4*)(g_Z + off) = v;
            *(float4*)(g_zinit + off) = v;
            *(float4*)(g_zsum + off) = make_float4(0.f, 0.f, 0.f, 0.f);
        } else if (MODE == 1) {
            float d = g_dis[grow];
            size_t off = (size_t)grow * 128 + cb;
            __half2 h0 = __floats2half2_rn(u0.x * d, u0.y * d);
            __half2 h1 = __floats2half2_rn(u1.x * d, u1.y * d);
            uint2 st;
            st.x = *(uint32_t*)&h0;
            st.y = *(uint32_t*)&h1;
            *(uint2*)((__half*)g_yh + off) = st;
        } else {
            size_t off = (size_t)grow * OUTD + cb;
            *(float4*)(C + off) = make_float4(u0.x + bv.x, u0.y + bv.y,
                                              u1.x + bv.z, u1.y + bv.w);
        }
    }
}

// ---------------- aggregation: one warp per dst node, fp16 gather ----------------
// Z[d] = relu( dis[d]*( sum_{s in nbr(d)} y[s] + y[d] ) + b ); zsum[d] += Z[d]
__global__ void k_agg(const float* __restrict__ bias) {
    int warp = (blockIdx.x * blockDim.x + threadIdx.x) >> 5;
    int lane = threadIdx.x & 31;
    if (warp >= NN) return;
    int d = warp;
    int start = g_rowptr[d];
    int len = g_deg[d];
    const uint2* y2 = (const uint2*)g_yh;   // 4 halves per lane
    float4 acc;
    {
        uint2 raw = y2[(size_t)d * 32 + lane];  // self term y[d]
        __half2 h0 = *(__half2*)&raw.x, h1 = *(__half2*)&raw.y;
        float2 f0 = __half22float2(h0), f1 = __half22float2(h1);
        acc = make_float4(f0.x, f0.y, f1.x, f1.y);
    }
    int end = start + len;
    for (int j0 = start; j0 < end; j0 += 32) {
        int c = (j0 + lane < end) ? g_col[j0 + lane] : 0;
        int m = end - j0; if (m > 32) m = 32;
        for (int t = 0; t < m; t++) {
            int s = __shfl_sync(0xffffffffu, c, t);
            uint2 raw = y2[(size_t)s * 32 + lane];
            __half2 h0 = *(__half2*)&raw.x, h1 = *(__half2*)&raw.y;
            float2 f0 = __half22float2(h0), f1 = __half22float2(h1);
            acc.x += f0.x; acc.y += f0.y; acc.z += f1.x; acc.w += f1.y;
        }
    }
    float dd = g_dis[d];
    float4 b4 = ((const float4*)bias)[lane];
    float4 o;
    o.x = fmaxf(fmaf(dd, acc.x, b4.x), 0.f);
    o.y = fmaxf(fmaf(dd, acc.y, b4.y), 0.f);
    o.z = fmaxf(fmaf(dd, acc.z, b4.z), 0.f);
    o.w = fmaxf(fmaf(dd, acc.w, b4.w), 0.f);
    ((float4*)g_Z)[(size_t)d * 32 + lane] = o;
    float4* zs4 = (float4*)g_zsum;
    float4 zs = zs4[(size_t)d * 32 + lane];
    zs.x += o.x; zs.y += o.y; zs.z += o.z; zs.w += o.w;
    zs4[(size_t)d * 32 + lane] = zs;
}

// ---------------- launch ----------------
extern "C" void kernel_launch(void* const* d_in, const int* in_sizes, int n_in,
                              void* d_out, int out_size) {
    const float* x     = (const float*)d_in[0];
    const void*  ei    = d_in[1];
    const float* W1    = (const float*)d_in[2];
    const float* b1    = (const float*)d_in[3];
    const float* convW = (const float*)d_in[4];
    const float* convB = (const float*)d_in[5];
    const float* W2    = (const float*)d_in[6];
    const float* b2    = (const float*)d_in[7];
    float* out = (float*)d_out;

    const int NB_N = (NN + 255) / 256;
    const int NB_E = (EE + 255) / 256;
    const int NB_SCAN = (NN + 1023) / 1024;
    const int NB_MM = (NN + 127) / 128;       // 782
    const int NB_AGG = (NN * 32 + 255) / 256;

    const int SM128 = (128 * 128 + 128 * 128) * 4;  // 131072
    const int SM64  = (128 * 128 + 128 * 64) * 4;   //  98304
    cudaFuncSetAttribute(k_mm<128, 0>, cudaFuncAttributeMaxDynamicSharedMemorySize, SM128);
    cudaFuncSetAttribute(k_mm<128, 1>, cudaFuncAttributeMaxDynamicSharedMemorySize, SM128);
    cudaFuncSetAttribute(k_mm<64, 2>,  cudaFuncAttributeMaxDynamicSharedMemorySize, SM64);

    // order chosen so launch #4 (the one ncu -s5 -c1 captures) is the mode-0 GEMM
    k_detect<<<1, 32>>>(ei);
    k_zero<<<NB_N, 256>>>();
    k_hist<<<NB_E, 256>>>(ei);
    k_mm<128, 0><<<NB_MM, 512, SM128>>>(x, W1, b1, nullptr);
    k_dis<<<NB_N, 256>>>();
    k_scan1<<<NB_SCAN, 256>>>();
    k_scan2<<<1, 128>>>(NB_SCAN);
    k_scan3<<<NB_N, 256>>>();
    k_fill<<<NB_E, 256>>>(ei);

    for (int l = 0; l < 4; l++) {
        k_mm<128, 1><<<NB_MM, 512, SM128>>>(nullptr, convW + (size_t)l * HH * HH,
                                            nullptr, nullptr);
        k_agg<<<NB_AGG, 256>>>(convB + (size_t)l * HH);
    }

    k_mm<64, 2><<<NB_MM, 512, SM64>>>(nullptr, W2, b2, out);
}

// round 13
// speedup vs baseline: 1.3376x; 1.1373x over previous
#include <cuda_runtime.h>
#include <cuda_fp16.h>
#include <cstdint>

#define NN 100000
#define HH 128
#define EE 1600000
#define OUTD 64
#define ALPHA_C 0.6f
#define BETA_C 0.1f   // (1-ALPHA)/L

// ---------------- scratch (device globals: allocation-free) ----------------
__device__ float  g_Z[(size_t)NN * HH];     // activations written by agg
__device__ __half g_yh[(size_t)NN * HH];    // y = (Z@W)*dis[row], fp16
__device__ float  g_zinit[(size_t)NN * HH];
__device__ float  g_zsum[(size_t)NN * HH];
__device__ float  g_dis[NN];
__device__ int    g_deg[NN];
__device__ int    g_cnt[NN];
__device__ int    g_rowptr[NN];
__device__ int    g_col[EE];
__device__ int    g_bsum[128];
__device__ int    g_is64;

// ---------------- f32x2 helpers ----------------
__device__ __forceinline__ unsigned long long bcast2(float v) {
    unsigned long long r;
    asm("mov.b64 %0, {%1, %1};" : "=l"(r) : "f"(v));
    return r;
}
__device__ __forceinline__ void fma2(unsigned long long& acc, unsigned long long a,
                                     unsigned long long b) {
    asm("fma.rn.f32x2 %0, %1, %2, %0;" : "+l"(acc) : "l"(a), "l"(b));
}
__device__ __forceinline__ float2 unpk(unsigned long long v) {
    float2 r;
    asm("mov.b64 {%0, %1}, %2;" : "=f"(r.x), "=f"(r.y) : "l"(v));
    return r;
}

// ---------------- edge dtype detection ----------------
__global__ void k_detect(const void* ei) {
    if (threadIdx.x == 0) {
        const long long* p = (const long long*)ei;
        int is64 = 1;
        for (int i = 0; i < 64; i++) {
            long long v = p[i];
            if (v < 0 || v >= NN) { is64 = 0; break; }
        }
        g_is64 = is64;
    }
}

__device__ __forceinline__ int edge_at(const void* ei, long long i) {
    return g_is64 ? (int)((const long long*)ei)[i] : ((const int*)ei)[i];
}

// ---------------- CSR build ----------------
__global__ void k_zero() {
    int i = blockIdx.x * blockDim.x + threadIdx.x;
    if (i < NN) { g_deg[i] = 0; g_cnt[i] = 0; }
}

__global__ void k_hist(const void* ei) {
    int e = blockIdx.x * blockDim.x + threadIdx.x;
    if (e < EE) atomicAdd(&g_deg[edge_at(ei, (long long)EE + e)], 1);
}

__global__ void k_dis() {
    int i = blockIdx.x * blockDim.x + threadIdx.x;
    if (i < NN) g_dis[i] = rsqrtf((float)g_deg[i] + 1.0f);
}

__global__ void k_scan1() {
    __shared__ int sm[256];
    int b = blockIdx.x, t = threadIdx.x;
    int base = b * 1024 + t * 4;
    int v[4];
#pragma unroll
    for (int j = 0; j < 4; j++) {
        int i = base + j;
        v[j] = (i < NN) ? g_deg[i] : 0;
    }
    int s = v[0] + v[1] + v[2] + v[3];
    sm[t] = s;
    __syncthreads();
    for (int off = 1; off < 256; off <<= 1) {
        int x = sm[t];
        if (t >= off) x += sm[t - off];
        __syncthreads();
        sm[t] = x;
        __syncthreads();
    }
    int ex = sm[t] - s;
    int run = 0;
#pragma unroll
    for (int j = 0; j < 4; j++) {
        int i = base + j;
        if (i < NN) g_rowptr[i] = ex + run;
        run += v[j];
    }
    if (t == 255) g_bsum[b] = sm[255];
}

__global__ void k_scan2(int nb) {
    __shared__ int sm[128];
    int t = threadIdx.x;
    int v = (t < nb) ? g_bsum[t] : 0;
    sm[t] = v;
    __syncthreads();
    for (int off = 1; off < 128; off <<= 1) {
        int x = sm[t];
        if (t >= off) x += sm[t - off];
        __syncthreads();
        sm[t] = x;
        __syncthreads();
    }
    g_bsum[t] = sm[t] - v;
}

__global__ void k_scan3() {
    int i = blockIdx.x * blockDim.x + threadIdx.x;
    if (i < NN) g_rowptr[i] += g_bsum[i >> 10];
}

__global__ void k_fill(const void* ei) {
    int e = blockIdx.x * blockDim.x + threadIdx.x;
    if (e >= EE) return;
    int s = edge_at(ei, e);
    int d = edge_at(ei, (long long)EE + e);
    int pos = g_rowptr[d] + atomicAdd(&g_cnt[d], 1);
    g_col[pos] = s;
}

// ---------------- GEMM: 64 x 128 @ 128 x BN, 256 thr, 2 CTAs/SM ----------------
// MODE 0: g_zinit = x@W + bias                 (A = x param)
// MODE 1: g_yh = fp16( (src@W) * dis[row] ),   src = g_zinit (SRC=1) or g_Z (SRC=2)
// MODE 2: out = (ALPHA*zinit + BETA*zsum)@W + bias
template <int BN, int MODE, int SRC>
__global__ void __launch_bounds__(256, 2) k_mm(const float* __restrict__ A,
                                               const float* __restrict__ W,
                                               const float* __restrict__ bias,
                                               float* __restrict__ C) {
    extern __shared__ float sm[];
    float* As = sm;              // 64*128 floats (32KB)
    float* Bs = sm + 64 * 128;   // 128*BN floats

    constexpr int CPG = BN / 4;          // column groups (32 or 16)
    constexpr int RM = 64 * CPG / 256;   // rows per thread (8 or 4)

    int tid = threadIdx.x;
    int row0 = blockIdx.x * 64;

    // ---- load A tile (64 x 128, identity layout, coalesced) ----
#pragma unroll
    for (int it = 0; it < 8; it++) {
        int f4 = it * 256 + tid;        // float4 index 0..2047
        int r = f4 >> 5;                // row 0..63
        int grow = row0 + r;
        float4 v = make_float4(0.f, 0.f, 0.f, 0.f);
        if (grow < NN) {
            size_t off = (size_t)grow * 128 + ((f4 & 31) << 2);
            if (MODE == 0) {
                v = *(const float4*)(A + off);
            } else if (MODE == 1) {
                v = *(const float4*)((SRC == 1 ? g_zinit : g_Z) + off);
            } else {
                float4 zi = *(const float4*)(g_zinit + off);
                float4 zs = *(const float4*)(g_zsum + off);
                v.x = ALPHA_C * zi.x + BETA_C * zs.x;
                v.y = ALPHA_C * zi.y + BETA_C * zs.y;
                v.z = ALPHA_C * zi.z + BETA_C * zs.z;
                v.w = ALPHA_C * zi.w + BETA_C * zs.w;
            }
        }
        *(float4*)&As[(size_t)f4 << 2] = v;
    }
    // ---- load full B (identity copy) ----
#pragma unroll
    for (int it = 0; it < (128 * BN) / 1024; it++) {
        int f4 = it * 256 + tid;
        *(float4*)&Bs[(size_t)f4 << 2] = *(const float4*)(W + ((size_t)f4 << 2));
    }
    __syncthreads();

    int cg = tid & (CPG - 1);
    int rg = tid / CPG;
    int rb = rg * RM;
    int cb = cg * 4;

    unsigned long long acc2[RM][2];
#pragma unroll
    for (int i = 0; i < RM; i++) { acc2[i][0] = 0ULL; acc2[i][1] = 0ULL; }

#pragma unroll 4
    for (int kk = 0; kk < 32; kk++) {
        float4 af[RM];
#pragma unroll
        for (int i = 0; i < RM; i++)
            af[i] = *(float4*)&As[(rb + i) * 128 + kk * 4];
#pragma unroll
        for (int j = 0; j < 4; j++) {
            int k = kk * 4 + j;
            ulonglong2 p = *(ulonglong2*)&Bs[k * BN + cb];
#pragma unroll
            for (int i = 0; i < RM; i++) {
                float a = (j == 0) ? af[i].x : (j == 1) ? af[i].y
                        : (j == 2) ? af[i].z : af[i].w;
                unsigned long long a2 = bcast2(a);
                fma2(acc2[i][0], a2, p.x);
                fma2(acc2[i][1], a2, p.y);
            }
        }
    }

    // ---- epilogue ----
    float4 bv = make_float4(0.f, 0.f, 0.f, 0.f);
    if (MODE != 1) bv = *(const float4*)(bias + cb);
#pragma unroll
    for (int i = 0; i < RM; i++) {
        int grow = row0 + rb + i;
        if (grow >= NN) continue;
        float2 u0 = unpk(acc2[i][0]);
        float2 u1 = unpk(acc2[i][1]);
        if (MODE == 0) {
            size_t off = (size_t)grow * 128 + cb;
            *(float4*)(g_zinit + off) = make_float4(u0.x + bv.x, u0.y + bv.y,
                                                    u1.x + bv.z, u1.y + bv.w);
        } else if (MODE == 1) {
            float d = g_dis[grow];
            size_t off = (size_t)grow * 128 + cb;
            __half2 h0 = __floats2half2_rn(u0.x * d, u0.y * d);
            __half2 h1 = __floats2half2_rn(u1.x * d, u1.y * d);
            uint2 st;
            st.x = *(uint32_t*)&h0;
            st.y = *(uint32_t*)&h1;
            *(uint2*)((__half*)g_yh + off) = st;
        } else {
            size_t off = (size_t)grow * OUTD + cb;
            *(float4*)(C + off) = make_float4(u0.x + bv.x, u0.y + bv.y,
                                              u1.x + bv.z, u1.y + bv.w);
        }
    }
}

// ---------------- aggregation: one warp per dst node, fp16 gather ----------------
// Z[d] = relu( dis[d]*( sum_nbr y[s] + y[d] ) + b ); zsum = o (FIRST) or += o
template <int FIRST>
__global__ void k_agg(const float* __restrict__ bias) {
    int warp = (blockIdx.x * blockDim.x + threadIdx.x) >> 5;
    int lane = threadIdx.x & 31;
    if (warp >= NN) return;
    int d = warp;
    int start = g_rowptr[d];
    int len = g_deg[d];
    const uint2* y2 = (const uint2*)g_yh;   // 4 halves per lane
    float4 acc;
    {
        uint2 raw = y2[(size_t)d * 32 + lane];  // self term y[d]
        __half2 h0 = *(__half2*)&raw.x, h1 = *(__half2*)&raw.y;
        float2 f0 = __half22float2(h0), f1 = __half22float2(h1);
        acc = make_float4(f0.x, f0.y, f1.x, f1.y);
    }
    int end = start + len;
    for (int j0 = start; j0 < end; j0 += 32) {
        int c = (j0 + lane < end) ? g_col[j0 + lane] : 0;
        int m = end - j0; if (m > 32) m = 32;
        for (int t = 0; t < m; t++) {
            int s = __shfl_sync(0xffffffffu, c, t);
            uint2 raw = y2[(size_t)s * 32 + lane];
            __half2 h0 = *(__half2*)&raw.x, h1 = *(__half2*)&raw.y;
            float2 f0 = __half22float2(h0), f1 = __half22float2(h1);
            acc.x += f0.x; acc.y += f0.y; acc.z += f1.x; acc.w += f1.y;
        }
    }
    float dd = g_dis[d];
    float4 b4 = ((const float4*)bias)[lane];
    float4 o;
    o.x = fmaxf(fmaf(dd, acc.x, b4.x), 0.f);
    o.y = fmaxf(fmaf(dd, acc.y, b4.y), 0.f);
    o.z = fmaxf(fmaf(dd, acc.z, b4.z), 0.f);
    o.w = fmaxf(fmaf(dd, acc.w, b4.w), 0.f);
    ((float4*)g_Z)[(size_t)d * 32 + lane] = o;
    float4* zs4 = (float4*)g_zsum;
    if (FIRST) {
        zs4[(size_t)d * 32 + lane] = o;
    } else {
        float4 zs = zs4[(size_t)d * 32 + lane];
        zs.x += o.x; zs.y += o.y; zs.z += o.z; zs.w += o.w;
        zs4[(size_t)d * 32 + lane] = zs;
    }
}

// ---------------- launch ----------------
extern "C" void kernel_launch(void* const* d_in, const int* in_sizes, int n_in,
                              void* d_out, int out_size) {
    const float* x     = (const float*)d_in[0];
    const void*  ei    = d_in[1];
    const float* W1    = (const float*)d_in[2];
    const float* b1    = (const float*)d_in[3];
    const float* convW = (const float*)d_in[4];
    const float* convB = (const float*)d_in[5];
    const float* W2    = (const float*)d_in[6];
    const float* b2    = (const float*)d_in[7];
    float* out = (float*)d_out;

    const int NB_N = (NN + 255) / 256;
    const int NB_E = (EE + 255) / 256;
    const int NB_SCAN = (NN + 1023) / 1024;
    const int NB_MM = (NN + 63) / 64;         // 1563
    const int NB_AGG = (NN * 32 + 255) / 256;

    const int SM128 = (64 * 128 + 128 * 128) * 4;  // 98304 (96KB)
    const int SM64  = (64 * 128 + 128 * 64) * 4;   // 65536 (64KB)
    cudaFuncSetAttribute(k_mm<128, 0, 0>, cudaFuncAttributeMaxDynamicSharedMemorySize, SM128);
    cudaFuncSetAttribute(k_mm<128, 1, 1>, cudaFuncAttributeMaxDynamicSharedMemorySize, SM128);
    cudaFuncSetAttribute(k_mm<128, 1, 2>, cudaFuncAttributeMaxDynamicSharedMemorySize, SM128);
    cudaFuncSetAttribute(k_mm<64, 2, 0>,  cudaFuncAttributeMaxDynamicSharedMemorySize, SM64);

    // order chosen so launch #4 (the one ncu -s5 -c1 captures) is the mode-0 GEMM
    k_detect<<<1, 32>>>(ei);
    k_zero<<<NB_N, 256>>>();
    k_hist<<<NB_E, 256>>>(ei);
    k_mm<128, 0, 0><<<NB_MM, 256, SM128>>>(x, W1, b1, nullptr);
    k_dis<<<NB_N, 256>>>();
    k_scan1<<<NB_SCAN, 256>>>();
    k_scan2<<<1, 128>>>(NB_SCAN);
    k_scan3<<<NB_N, 256>>>();
    k_fill<<<NB_E, 256>>>(ei);

    // layer 0: y from zinit; agg stores zsum
    k_mm<128, 1, 1><<<NB_MM, 256, SM128>>>(nullptr, convW, nullptr, nullptr);
    k_agg<1><<<NB_AGG, 256>>>(convB);

    for (int l = 1; l < 4; l++) {
        k_mm<128, 1, 2><<<NB_MM, 256, SM128>>>(nullptr, convW + (size_t)l * HH * HH,
                                               nullptr, nullptr);
        k_agg<0><<<NB_AGG, 256>>>(convB + (size_t)l * HH);
    }

    k_mm<64, 2, 0><<<NB_MM, 256, SM64>>>(nullptr, W2, b2, out);
}